// round 13
// baseline (speedup 1.0000x reference)
#include <cuda_runtime.h>
#include <cuda_bf16.h>
#include <cstdint>

// ============================================================================
// Problem constants
// ============================================================================
static constexpr int NN = 16384;   // fine nodes
static constexpr int MM = 4096;    // coarse nodes
static constexpr int DD = 256;     // feature dim
static constexpr int OO = 256;     // output dim

// Factorization:
//   exp(masked_ij) = 1 + adj_ij*(a_i*b_j - 1),  a_i = exp(sf_i + ba), b_j = exp(sc_j)
//   With G = Hc@Wt^T, SW = colsum(G):
//   out = relu( Hf@Wt^T + (SW + a_i*U' - V')/Z_i + bt )
//   U' = adj@(b.*G), V' = adj@G, Z_i = (M - v_i) + a_i*u_i, u=adj@b, v=adj@1
// Big GEMM (fused): Ct rows interleaved (2c = b.*G col c, 2c+1 = G col c) so
//   each acc pair is (U'_c, V'_c); epilogue computes out directly.
// This round: ONE sync per K-iter, with the next-stage cp.async burst issued
//   right after the barrier (compute body stays pure ldmatrix+MMA).

// ============================================================================
// Static device scratch (no allocations allowed)
// ============================================================================
__device__ __nv_bfloat16 g_adjbf[(size_t)NN * MM];     // 128 MB, exact 0/1
__device__ __nv_bfloat16 g_Ct[(size_t)512 * 4096];     // 4 MB, interleaved
__device__ __nv_bfloat16 g_A2[(size_t)NN * 768];       // 24 MB
__device__ __nv_bfloat16 g_B2[(size_t)OO * 768];       // 384 KB
__device__ float g_G[(size_t)MM * OO];                 // 4 MB
__device__ float g_HW[(size_t)NN * OO];                // 16 MB
__device__ float g_a[NN];
__device__ float g_b[MM];
__device__ float g_u[NN];
__device__ float g_v[NN];
__device__ float g_SW[OO];
__device__ float g_SWp[32 * OO];

// ============================================================================
// Helpers
// ============================================================================
#define SWZ128(off) ((off) ^ (((off) >> 3) & 0x70))

static __device__ __forceinline__ uint32_t smem_u32(const void* p) {
    uint32_t a;
    asm("{ .reg .u64 t; cvta.to.shared.u64 t, %1; cvt.u32.u64 %0, t; }"
        : "=r"(a) : "l"(p));
    return a;
}

static __device__ __forceinline__ void cp_async16(uint32_t saddr, const void* gaddr) {
    asm volatile("cp.async.cg.shared.global [%0], [%1], 16;"
                 :: "r"(saddr), "l"(gaddr));
}
static __device__ __forceinline__ void cp_commit() {
    asm volatile("cp.async.commit_group;");
}
template <int N>
static __device__ __forceinline__ void cp_wait() {
    asm volatile("cp.async.wait_group %0;" :: "n"(N));
}

static __device__ __forceinline__ void ldsm_x4(uint32_t* r, uint32_t addr) {
    asm volatile("ldmatrix.sync.aligned.m8n8.x4.shared.b16 {%0,%1,%2,%3}, [%4];"
                 : "=r"(r[0]), "=r"(r[1]), "=r"(r[2]), "=r"(r[3]) : "r"(addr));
}

static __device__ __forceinline__ void mma16816(float* d, const uint32_t* a,
                                                uint32_t b0, uint32_t b1) {
    asm volatile(
        "mma.sync.aligned.m16n8k16.row.col.f32.bf16.bf16.f32 "
        "{%0,%1,%2,%3}, {%4,%5,%6,%7}, {%8,%9}, {%0,%1,%2,%3};"
        : "+f"(d[0]), "+f"(d[1]), "+f"(d[2]), "+f"(d[3])
        : "r"(a[0]), "r"(a[1]), "r"(a[2]), "r"(a[3]), "r"(b0), "r"(b1));
}

// ============================================================================
// Prep kernels
// ============================================================================

// out[r] = exp( dot(X[r,:256], w) + bias ), one warp per row
__global__ void row_dot_exp(const float* __restrict__ X, const float* __restrict__ w,
                            const float* __restrict__ bias, float* __restrict__ out, int rows) {
    int gw   = (blockIdx.x * blockDim.x + threadIdx.x) >> 5;
    int lane = threadIdx.x & 31;
    if (gw >= rows) return;
    const float* x = X + (size_t)gw * DD;
    float s = 0.f;
    #pragma unroll
    for (int k = lane; k < DD; k += 32) s += x[k] * w[k];
    #pragma unroll
    for (int o = 16; o; o >>= 1) s += __shfl_xor_sync(0xffffffffu, s, o);
    if (lane == 0) {
        float b = bias ? bias[0] : 0.f;
        out[gw] = expf(s + b);
    }
}

// G = Hc @ Wt^T  (fp32, 8 rows per block)
__global__ void gemm_G(const float* __restrict__ Hc, const float* __restrict__ Wt,
                       float* __restrict__ G) {
    __shared__ float sH[8][DD];
    int r0 = blockIdx.x * 8;
    for (int idx = threadIdx.x; idx < 8 * DD; idx += 256)
        sH[idx >> 8][idx & 255] = Hc[(size_t)r0 * DD + idx];
    __syncthreads();
    int o = threadIdx.x;
    float acc[8];
    #pragma unroll
    for (int r = 0; r < 8; r++) acc[r] = 0.f;
    const float* wrow = Wt + (size_t)o * DD;
    for (int k = 0; k < DD; k++) {
        float w = __ldg(wrow + k);
        #pragma unroll
        for (int r = 0; r < 8; r++) acc[r] += sH[r][k] * w;
    }
    #pragma unroll
    for (int r = 0; r < 8; r++) G[(size_t)(r0 + r) * OO + o] = acc[r];
}

// Column sums of G, two stages (deterministic, no atomics)
__global__ void sw_stage1(const float* __restrict__ G, float* __restrict__ part) {
    int o = threadIdx.x, bb = blockIdx.x;
    float s = 0.f;
    for (int k = bb * 128; k < bb * 128 + 128; k++) s += G[(size_t)k * OO + o];
    part[bb * OO + o] = s;
}
__global__ void sw_stage2(const float* __restrict__ part, float* __restrict__ SW) {
    int o = threadIdx.x;
    float s = 0.f;
    for (int p = 0; p < 32; p++) s += part[p * OO + o];
    SW[o] = s;
}

// Interleaved Ct: row 2c = bf16(b_k * G[k,c]) (U'), row 2c+1 = bf16(G[k,c]) (V')
__global__ void build_Ct(const float* __restrict__ b, const float* __restrict__ G,
                         __nv_bfloat16* __restrict__ Ct) {
    int k = blockIdx.x * 256 + threadIdx.x;  // 0..4095
    int c = blockIdx.y;                      // 0..511 (interleaved row index)
    int oc = c >> 1;
    float g = G[(size_t)k * OO + oc];
    float val = (c & 1) ? g : b[k] * g;
    Ct[(size_t)c * 4096 + k] = __float2bfloat16(val);
}

// adj fp32 -> bf16 (exact, values are 0/1), fused per-row u = adj@b, v = adj@1
__global__ void conv_adj(const float* __restrict__ adj, const float* __restrict__ b,
                         __nv_bfloat16* __restrict__ abf,
                         float* __restrict__ u, float* __restrict__ v) {
    int i = blockIdx.x;
    int t = threadIdx.x, lane = t & 31, wid = t >> 5;
    const float4* row = reinterpret_cast<const float4*>(adj + (size_t)i * MM);
    const float4* b4  = reinterpret_cast<const float4*>(b);
    uint2* dst = reinterpret_cast<uint2*>(abf + (size_t)i * MM);
    float su = 0.f, sv = 0.f;
    #pragma unroll
    for (int c = 0; c < 4; c++) {
        int j = c * 256 + t;
        float4 x  = row[j];
        float4 bb = b4[j];
        su += x.x * bb.x + x.y * bb.y + x.z * bb.z + x.w * bb.w;
        sv += x.x + x.y + x.z + x.w;
        __nv_bfloat162 p0 = __floats2bfloat162_rn(x.x, x.y);
        __nv_bfloat162 p1 = __floats2bfloat162_rn(x.z, x.w);
        uint2 o;
        o.x = *reinterpret_cast<unsigned*>(&p0);
        o.y = *reinterpret_cast<unsigned*>(&p1);
        dst[j] = o;
    }
    #pragma unroll
    for (int o = 16; o; o >>= 1) {
        su += __shfl_xor_sync(0xffffffffu, su, o);
        sv += __shfl_xor_sync(0xffffffffu, sv, o);
    }
    __shared__ float s1[8], s2[8];
    if (lane == 0) { s1[wid] = su; s2[wid] = sv; }
    __syncthreads();
    if (t == 0) {
        float a = 0.f, c = 0.f;
        #pragma unroll
        for (int w = 0; w < 8; w++) { a += s1[w]; c += s2[w]; }
        u[i] = a; v[i] = c;
    }
}

// A2[i, 0:256)=hi(Hf), [256:512)=hi(Hf), [512:768)=lo(Hf)
__global__ void build_A2(const float* __restrict__ Hf, __nv_bfloat16* __restrict__ A2) {
    int i = blockIdx.x, d = threadIdx.x;
    float x = Hf[(size_t)i * DD + d];
    __nv_bfloat16 hi = __float2bfloat16(x);
    __nv_bfloat16 lo = __float2bfloat16(x - __bfloat162float(hi));
    size_t base = (size_t)i * 768;
    A2[base + d]       = hi;
    A2[base + 256 + d] = hi;
    A2[base + 512 + d] = lo;
}
// B2[o, 0:256)=hi(Wt), [256:512)=lo(Wt), [512:768)=hi(Wt)
__global__ void build_B2(const float* __restrict__ Wt, __nv_bfloat16* __restrict__ B2) {
    int o = blockIdx.x, d = threadIdx.x;
    float x = Wt[(size_t)o * DD + d];
    __nv_bfloat16 hi = __float2bfloat16(x);
    __nv_bfloat16 lo = __float2bfloat16(x - __bfloat162float(hi));
    size_t base = (size_t)o * 768;
    B2[base + d]       = hi;
    B2[base + 256 + d] = lo;
    B2[base + 512 + d] = hi;
}

// ============================================================================
// bf16 mma.sync GEMM, 3-stage cp.async pipeline (BM=128, BN=128, BK=64)
// One sync per iteration; next-stage burst issued right after the barrier.
// Plain version (HW GEMM): writes C fp32.
// ============================================================================
static constexpr int STAGES      = 3;
static constexpr int STAGE_BYTES = 32768;
static constexpr int SMEM_GEMM   = STAGES * STAGE_BYTES;  // 96KB

__global__ void __launch_bounds__(256, 2)
gemm_bf16_mma(const __nv_bfloat16* __restrict__ A, int lda,
              const __nv_bfloat16* __restrict__ B, int ldb,
              float* __restrict__ C, int ldc, int Ktot) {
    extern __shared__ char smem[];
    const uint32_t sb = smem_u32(smem);
    const int tid  = threadIdx.x;
    const int wid  = tid >> 5, lane = tid & 31;
    const int wm   = wid >> 2, wn = wid & 3;
    const int m0   = blockIdx.y * 128;
    const int n0   = blockIdx.x * 128;

    float acc[4][4][4];
    #pragma unroll
    for (int i = 0; i < 4; i++)
        #pragma unroll
        for (int j = 0; j < 4; j++)
            #pragma unroll
            for (int q = 0; q < 4; q++) acc[i][j][q] = 0.f;

    const int r  = tid >> 3;
    const int cc = tid & 7;
    const int niter = Ktot / 64;

    auto load_stage = [&](int it) {
        const int k0 = it * 64;
        const uint32_t sA = sb + (it % STAGES) * STAGE_BYTES;
        const uint32_t sB = sA + 16384;
        #pragma unroll
        for (int rep = 0; rep < 4; rep++) {
            uint32_t off = SWZ128((uint32_t)((r + rep * 32) * 128 + cc * 16));
            cp_async16(sA + off, A + (size_t)(m0 + r + rep * 32) * lda + k0 + cc * 8);
            cp_async16(sB + off, B + (size_t)(n0 + r + rep * 32) * ldb + k0 + cc * 8);
        }
        cp_commit();
    };

    load_stage(0);
    if (niter > 1) load_stage(1);

    const int arow = wm * 64 + (lane & 15);
    const int acol = ((lane >> 4) & 1) * 16;
    const int brow = wn * 32 + ((lane >> 4) & 1) * 8 + (lane & 7);
    const int bcol = ((lane >> 3) & 1) * 16;

    for (int it = 0; it < niter; ++it) {
        if (it + 1 < niter) cp_wait<1>();
        else cp_wait<0>();
        __syncthreads();   // all warps finished reading stage (it+2)%3 in it-1

        // Burst-issue next stage right after the barrier (safe to overwrite).
        if (it + 2 < niter) load_stage(it + 2);

        const uint32_t sA = sb + (it % STAGES) * STAGE_BYTES;
        const uint32_t sB = sA + 16384;

        #pragma unroll
        for (int kk = 0; kk < 4; kk++) {
            uint32_t a[4][4], b[2][4];
            #pragma unroll
            for (int mi = 0; mi < 4; mi++) {
                uint32_t off = SWZ128((uint32_t)((arow + mi * 16) * 128 + kk * 32 + acol));
                ldsm_x4(a[mi], sA + off);
            }
            #pragma unroll
            for (int nt = 0; nt < 2; nt++) {
                uint32_t off = SWZ128((uint32_t)((brow + nt * 16) * 128 + kk * 32 + bcol));
                ldsm_x4(b[nt], sB + off);
            }
            #pragma unroll
            for (int mi = 0; mi < 4; mi++)
                #pragma unroll
                for (int ni = 0; ni < 4; ni++)
                    mma16816(acc[mi][ni], a[mi],
                             b[ni >> 1][(ni & 1) * 2], b[ni >> 1][(ni & 1) * 2 + 1]);
        }
    }

    __syncthreads();

    const int g = lane >> 2, t = lane & 3;
    #pragma unroll
    for (int mi = 0; mi < 4; mi++) {
        #pragma unroll
        for (int ni = 0; ni < 4; ni++) {
            int row = m0 + wm * 64 + mi * 16 + g;
            int col = n0 + wn * 32 + ni * 8 + t * 2;
            float2* p0 = reinterpret_cast<float2*>(C + (size_t)row * ldc + col);
            float2* p1 = reinterpret_cast<float2*>(C + (size_t)(row + 8) * ldc + col);
            *p0 = make_float2(acc[mi][ni][0], acc[mi][ni][1]);
            *p1 = make_float2(acc[mi][ni][2], acc[mi][ni][3]);
        }
    }
}

// ============================================================================
// Big GEMM with FUSED final epilogue (same single-sync, burst-load mainloop).
//   A = adj bf16 [NN x 4096]; B = interleaved Ct [512 x 4096].
//   acc column pairs = (U'_c, V'_c), c = col>>1.
//   out[i,c] = relu( HW[i,c] + (SW[c] + a_i*U' - V') / Z_i + bt[c] )
// ============================================================================
__global__ void __launch_bounds__(256, 2)
gemm_big_fused(const __nv_bfloat16* __restrict__ A,
               const __nv_bfloat16* __restrict__ B,
               const float* __restrict__ HW,
               const float* __restrict__ av, const float* __restrict__ uv,
               const float* __restrict__ vv, const float* __restrict__ SW,
               const float* __restrict__ bt, float* __restrict__ out) {
    extern __shared__ char smem[];
    const uint32_t sb = smem_u32(smem);
    const int tid  = threadIdx.x;
    const int wid  = tid >> 5, lane = tid & 31;
    const int wm   = wid >> 2, wn = wid & 3;
    const int m0   = blockIdx.y * 128;
    const int n0   = blockIdx.x * 128;

    float acc[4][4][4];
    #pragma unroll
    for (int i = 0; i < 4; i++)
        #pragma unroll
        for (int j = 0; j < 4; j++)
            #pragma unroll
            for (int q = 0; q < 4; q++) acc[i][j][q] = 0.f;

    const int r  = tid >> 3;
    const int cc = tid & 7;
    const int niter = MM / 64;

    auto load_stage = [&](int it) {
        const int k0 = it * 64;
        const uint32_t sA = sb + (it % STAGES) * STAGE_BYTES;
        const uint32_t sB = sA + 16384;
        #pragma unroll
        for (int rep = 0; rep < 4; rep++) {
            uint32_t off = SWZ128((uint32_t)((r + rep * 32) * 128 + cc * 16));
            cp_async16(sA + off, A + (size_t)(m0 + r + rep * 32) * MM + k0 + cc * 8);
            cp_async16(sB + off, B + (size_t)(n0 + r + rep * 32) * MM + k0 + cc * 8);
        }
        cp_commit();
    };

    load_stage(0);
    load_stage(1);

    const int arow = wm * 64 + (lane & 15);
    const int acol = ((lane >> 4) & 1) * 16;
    const int brow = wn * 32 + ((lane >> 4) & 1) * 8 + (lane & 7);
    const int bcol = ((lane >> 3) & 1) * 16;

    for (int it = 0; it < niter; ++it) {
        if (it + 1 < niter) cp_wait<1>();
        else cp_wait<0>();
        __syncthreads();

        if (it + 2 < niter) load_stage(it + 2);

        const uint32_t sA = sb + (it % STAGES) * STAGE_BYTES;
        const uint32_t sB = sA + 16384;

        #pragma unroll
        for (int kk = 0; kk < 4; kk++) {
            uint32_t a[4][4], b[2][4];
            #pragma unroll
            for (int mi = 0; mi < 4; mi++) {
                uint32_t off = SWZ128((uint32_t)((arow + mi * 16) * 128 + kk * 32 + acol));
                ldsm_x4(a[mi], sA + off);
            }
            #pragma unroll
            for (int nt = 0; nt < 2; nt++) {
                uint32_t off = SWZ128((uint32_t)((brow + nt * 16) * 128 + kk * 32 + bcol));
                ldsm_x4(b[nt], sB + off);
            }
            #pragma unroll
            for (int mi = 0; mi < 4; mi++)
                #pragma unroll
                for (int ni = 0; ni < 4; ni++)
                    mma16816(acc[mi][ni], a[mi],
                             b[ni >> 1][(ni & 1) * 2], b[ni >> 1][(ni & 1) * 2 + 1]);
        }
    }

    // ---- fused final epilogue ----
    const int g = lane >> 2, t = lane & 3;
    #pragma unroll
    for (int mi = 0; mi < 4; mi++) {
        int row0 = m0 + wm * 64 + mi * 16 + g;
        int row1 = row0 + 8;
        float a0 = av[row0], a1 = av[row1];
        float iz0 = __fdividef(1.f, ((float)MM - vv[row0]) + a0 * uv[row0]);
        float iz1 = __fdividef(1.f, ((float)MM - vv[row1]) + a1 * uv[row1]);
        #pragma unroll
        for (int ni = 0; ni < 4; ni++) {
            int col = n0 + wn * 32 + ni * 8 + t * 2;   // even interleaved col
            int c   = col >> 1;                        // output column
            float sw = SW[c], btc = bt[c];
            float o0 = HW[(size_t)row0 * OO + c]
                     + (sw + a0 * acc[mi][ni][0] - acc[mi][ni][1]) * iz0 + btc;
            float o1 = HW[(size_t)row1 * OO + c]
                     + (sw + a1 * acc[mi][ni][2] - acc[mi][ni][3]) * iz1 + btc;
            out[(size_t)row0 * OO + c] = fmaxf(o0, 0.f);
            out[(size_t)row1 * OO + c] = fmaxf(o1, 0.f);
        }
    }
}

// ============================================================================
// Host launcher (serial; HW GEMM precedes the fused big GEMM)
// ============================================================================
extern "C" void kernel_launch(void* const* d_in, const int* in_sizes, int n_in,
                              void* d_out, int out_size) {
    const float* Hf  = (const float*)d_in[0];
    const float* Hc  = (const float*)d_in[1];
    const float* adj = (const float*)d_in[2];
    const float* wa  = (const float*)d_in[3];
    const float* ba  = (const float*)d_in[4];
    const float* Wt  = (const float*)d_in[5];
    const float* bt  = (const float*)d_in[6];
    float* out = (float*)d_out;

    (void)in_sizes; (void)n_in; (void)out_size;

    __nv_bfloat16 *adjbf, *Ct, *A2, *B2;
    float *G, *HW, *a, *b, *u, *v, *SW, *SWp;
    cudaGetSymbolAddress((void**)&adjbf, g_adjbf);
    cudaGetSymbolAddress((void**)&Ct,  g_Ct);
    cudaGetSymbolAddress((void**)&A2,  g_A2);
    cudaGetSymbolAddress((void**)&B2,  g_B2);
    cudaGetSymbolAddress((void**)&G,   g_G);
    cudaGetSymbolAddress((void**)&HW,  g_HW);
    cudaGetSymbolAddress((void**)&a,   g_a);
    cudaGetSymbolAddress((void**)&b,   g_b);
    cudaGetSymbolAddress((void**)&u,   g_u);
    cudaGetSymbolAddress((void**)&v,   g_v);
    cudaGetSymbolAddress((void**)&SW,  g_SW);
    cudaGetSymbolAddress((void**)&SWp, g_SWp);

    cudaFuncSetAttribute(gemm_bf16_mma,
                         cudaFuncAttributeMaxDynamicSharedMemorySize, SMEM_GEMM);
    cudaFuncSetAttribute(gemm_big_fused,
                         cudaFuncAttributeMaxDynamicSharedMemorySize, SMEM_GEMM);

    // [0,1] hi/lo splits for HW GEMM (need only raw inputs)
    build_A2<<<NN, 256>>>(Hf, A2);
    build_B2<<<OO, 256>>>(Wt, B2);
    // [2] HW = Hf @ Wt^T (3-term bf16, K=768)
    gemm_bf16_mma<<<dim3(2, NN / 128), 256, SMEM_GEMM>>>(
        A2, 768, B2, 768, HW, 256, 768);

    // [3] b_j = exp(Hc[j].wa[256:])
    row_dot_exp<<<(MM * 32 + 255) / 256, 256>>>(Hc, wa + DD, nullptr, b, MM);
    // [4] adj -> bf16, u = adj@b, v = adj@1
    conv_adj<<<NN, 256>>>(adj, b, adjbf, u, v);
    // [5] G = Hc @ Wt^T
    gemm_G<<<MM / 8, 256>>>(Hc, Wt, G);
    // [6] interleaved Ct
    build_Ct<<<dim3(16, 512), 256>>>(b, G, Ct);
    // [7] a_i = exp(Hf[i].wa[:256] + ba)
    row_dot_exp<<<(NN * 32 + 255) / 256, 256>>>(Hf, wa, ba, a, NN);
    // [8,9] SW = colsum(G)
    sw_stage1<<<32, 256>>>(G, SWp);
    sw_stage2<<<1, 256>>>(SWp, SW);

    // [10] BIG GEMM + fused final epilogue -> out
    gemm_big_fused<<<dim3(4, NN / 128), 256, SMEM_GEMM>>>(
        adjbf, Ct, HW, a, u, v, SW, bt, out);
}

// round 15
// speedup vs baseline: 1.0802x; 1.0802x over previous
#include <cuda_runtime.h>
#include <cuda_bf16.h>
#include <cstdint>

// ============================================================================
// Problem constants
// ============================================================================
static constexpr int NN = 16384;   // fine nodes
static constexpr int MM = 4096;    // coarse nodes
static constexpr int DD = 256;     // feature dim
static constexpr int OO = 256;     // output dim

// Factorization:
//   exp(masked_ij) = 1 + adj_ij*(a_i*b_j - 1),  a_i = exp(sf_i + ba), b_j = exp(sc_j)
//   With G = Hc@Wt^T, SW = colsum(G):
//   out = relu( Hf@Wt^T + (SW + a_i*U' - V')/Z_i + bt )
//   U' = adj@(b.*G), V' = adj@G, Z_i = (M - v_i) + a_i*u_i, u=adj@b, v=adj@1
// Big GEMM (fused): Ct rows interleaved (2c = b.*G col c, 2c+1 = G col c) so
//   each acc pair is (U'_c, V'_c); epilogue computes out directly.
// This round: GEMM mainloop reverted to the proven R10 structure; conv_adj
//   (DRAM-bound) overlapped on a side stream with the HW GEMM (tensor-bound)
//   and preps; a folded into build_A2; SW folded into build_Ct (atomics).

// ============================================================================
// Static device scratch (no allocations allowed)
// ============================================================================
__device__ __nv_bfloat16 g_adjbf[(size_t)NN * MM];     // 128 MB, exact 0/1
__device__ __nv_bfloat16 g_Ct[(size_t)512 * 4096];     // 4 MB, interleaved
__device__ __nv_bfloat16 g_A2[(size_t)NN * 768];       // 24 MB
__device__ __nv_bfloat16 g_B2[(size_t)OO * 768];       // 384 KB
__device__ float g_G[(size_t)MM * OO];                 // 4 MB
__device__ float g_HW[(size_t)NN * OO];                // 16 MB
__device__ float g_a[NN];
__device__ float g_b[MM];
__device__ float g_u[NN];
__device__ float g_v[NN];
__device__ float g_SW[OO];

// ============================================================================
// Helpers
// ============================================================================
#define SWZ128(off) ((off) ^ (((off) >> 3) & 0x70))

static __device__ __forceinline__ uint32_t smem_u32(const void* p) {
    uint32_t a;
    asm("{ .reg .u64 t; cvta.to.shared.u64 t, %1; cvt.u32.u64 %0, t; }"
        : "=r"(a) : "l"(p));
    return a;
}

static __device__ __forceinline__ void cp_async16(uint32_t saddr, const void* gaddr) {
    asm volatile("cp.async.cg.shared.global [%0], [%1], 16;"
                 :: "r"(saddr), "l"(gaddr));
}
static __device__ __forceinline__ void cp_commit() {
    asm volatile("cp.async.commit_group;");
}
template <int N>
static __device__ __forceinline__ void cp_wait() {
    asm volatile("cp.async.wait_group %0;" :: "n"(N));
}

static __device__ __forceinline__ void ldsm_x4(uint32_t* r, uint32_t addr) {
    asm volatile("ldmatrix.sync.aligned.m8n8.x4.shared.b16 {%0,%1,%2,%3}, [%4];"
                 : "=r"(r[0]), "=r"(r[1]), "=r"(r[2]), "=r"(r[3]) : "r"(addr));
}

static __device__ __forceinline__ void mma16816(float* d, const uint32_t* a,
                                                uint32_t b0, uint32_t b1) {
    asm volatile(
        "mma.sync.aligned.m16n8k16.row.col.f32.bf16.bf16.f32 "
        "{%0,%1,%2,%3}, {%4,%5,%6,%7}, {%8,%9}, {%0,%1,%2,%3};"
        : "+f"(d[0]), "+f"(d[1]), "+f"(d[2]), "+f"(d[3])
        : "r"(a[0]), "r"(a[1]), "r"(a[2]), "r"(a[3]), "r"(b0), "r"(b1));
}

// ============================================================================
// Prep kernels
// ============================================================================

// b_j = exp(Hc[j].wa2), one warp per row; block 0 also zeroes SW.
__global__ void prep_b(const float* __restrict__ Hc, const float* __restrict__ w,
                       float* __restrict__ b, float* __restrict__ SW) {
    if (blockIdx.x == 0 && threadIdx.x < OO) SW[threadIdx.x] = 0.f;
    int gw   = (blockIdx.x * blockDim.x + threadIdx.x) >> 5;
    int lane = threadIdx.x & 31;
    if (gw >= MM) return;
    const float* x = Hc + (size_t)gw * DD;
    float s = 0.f;
    #pragma unroll
    for (int k = lane; k < DD; k += 32) s += x[k] * w[k];
    #pragma unroll
    for (int o = 16; o; o >>= 1) s += __shfl_xor_sync(0xffffffffu, s, o);
    if (lane == 0) b[gw] = expf(s);
}

// G = Hc @ Wt^T  (fp32, 8 rows per block)
__global__ void gemm_G(const float* __restrict__ Hc, const float* __restrict__ Wt,
                       float* __restrict__ G) {
    __shared__ float sH[8][DD];
    int r0 = blockIdx.x * 8;
    for (int idx = threadIdx.x; idx < 8 * DD; idx += 256)
        sH[idx >> 8][idx & 255] = Hc[(size_t)r0 * DD + idx];
    __syncthreads();
    int o = threadIdx.x;
    float acc[8];
    #pragma unroll
    for (int r = 0; r < 8; r++) acc[r] = 0.f;
    const float* wrow = Wt + (size_t)o * DD;
    for (int k = 0; k < DD; k++) {
        float w = __ldg(wrow + k);
        #pragma unroll
        for (int r = 0; r < 8; r++) acc[r] += sH[r][k] * w;
    }
    #pragma unroll
    for (int r = 0; r < 8; r++) G[(size_t)(r0 + r) * OO + o] = acc[r];
}

// Interleaved Ct: row 2c = bf16(b_k*G[k,c]) (U'), row 2c+1 = bf16(G[k,c]) (V').
// V'-branch blocks also accumulate SW[c] = colsum(G) via block-reduce+atomicAdd.
__global__ void build_Ct(const float* __restrict__ b, const float* __restrict__ G,
                         __nv_bfloat16* __restrict__ Ct, float* __restrict__ SW) {
    int t = threadIdx.x;
    int k = blockIdx.x * 256 + t;            // 0..4095
    int c = blockIdx.y;                      // 0..511 (interleaved row index)
    int oc = c >> 1;
    float g = G[(size_t)k * OO + oc];
    float val = (c & 1) ? g : b[k] * g;
    Ct[(size_t)c * 4096 + k] = __float2bfloat16(val);
    if (c & 1) {
        // block reduction of g over 256 threads
        float s = g;
        #pragma unroll
        for (int o = 16; o; o >>= 1) s += __shfl_xor_sync(0xffffffffu, s, o);
        __shared__ float red[8];
        if ((t & 31) == 0) red[t >> 5] = s;
        __syncthreads();
        if (t == 0) {
            float tot = 0.f;
            #pragma unroll
            for (int w = 0; w < 8; w++) tot += red[w];
            atomicAdd(SW + oc, tot);
        }
    }
}

// adj fp32 -> bf16 (exact, values are 0/1), fused per-row u = adj@b, v = adj@1
__global__ void conv_adj(const float* __restrict__ adj, const float* __restrict__ b,
                         __nv_bfloat16* __restrict__ abf,
                         float* __restrict__ u, float* __restrict__ v) {
    int i = blockIdx.x;
    int t = threadIdx.x, lane = t & 31, wid = t >> 5;
    const float4* row = reinterpret_cast<const float4*>(adj + (size_t)i * MM);
    const float4* b4  = reinterpret_cast<const float4*>(b);
    uint2* dst = reinterpret_cast<uint2*>(abf + (size_t)i * MM);
    float su = 0.f, sv = 0.f;
    #pragma unroll
    for (int c = 0; c < 4; c++) {
        int j = c * 256 + t;
        float4 x  = row[j];
        float4 bb = b4[j];
        su += x.x * bb.x + x.y * bb.y + x.z * bb.z + x.w * bb.w;
        sv += x.x + x.y + x.z + x.w;
        __nv_bfloat162 p0 = __floats2bfloat162_rn(x.x, x.y);
        __nv_bfloat162 p1 = __floats2bfloat162_rn(x.z, x.w);
        uint2 o;
        o.x = *reinterpret_cast<unsigned*>(&p0);
        o.y = *reinterpret_cast<unsigned*>(&p1);
        dst[j] = o;
    }
    #pragma unroll
    for (int o = 16; o; o >>= 1) {
        su += __shfl_xor_sync(0xffffffffu, su, o);
        sv += __shfl_xor_sync(0xffffffffu, sv, o);
    }
    __shared__ float s1[8], s2[8];
    if (lane == 0) { s1[wid] = su; s2[wid] = sv; }
    __syncthreads();
    if (t == 0) {
        float a = 0.f, c = 0.f;
        #pragma unroll
        for (int w = 0; w < 8; w++) { a += s1[w]; c += s2[w]; }
        u[i] = a; v[i] = c;
    }
}

// A2 hi/lo split; also computes a_i = exp(Hf[i].wa + ba) (reuses the Hf read).
__global__ void build_A2_a(const float* __restrict__ Hf, const float* __restrict__ wa,
                           const float* __restrict__ ba,
                           __nv_bfloat16* __restrict__ A2, float* __restrict__ a) {
    int i = blockIdx.x, d = threadIdx.x;
    float x = Hf[(size_t)i * DD + d];
    __nv_bfloat16 hi = __float2bfloat16(x);
    __nv_bfloat16 lo = __float2bfloat16(x - __bfloat162float(hi));
    size_t base = (size_t)i * 768;
    A2[base + d]       = hi;
    A2[base + 256 + d] = hi;
    A2[base + 512 + d] = lo;
    // block-reduce dot(Hf_row, wa)
    float p = x * wa[d];
    #pragma unroll
    for (int o = 16; o; o >>= 1) p += __shfl_xor_sync(0xffffffffu, p, o);
    __shared__ float red[8];
    if ((d & 31) == 0) red[d >> 5] = p;
    __syncthreads();
    if (d == 0) {
        float s = 0.f;
        #pragma unroll
        for (int w = 0; w < 8; w++) s += red[w];
        a[i] = expf(s + ba[0]);
    }
}

// B2[o, 0:256)=hi(Wt), [256:512)=lo(Wt), [512:768)=hi(Wt)
__global__ void build_B2(const float* __restrict__ Wt, __nv_bfloat16* __restrict__ B2) {
    int o = blockIdx.x, d = threadIdx.x;
    float x = Wt[(size_t)o * DD + d];
    __nv_bfloat16 hi = __float2bfloat16(x);
    __nv_bfloat16 lo = __float2bfloat16(x - __bfloat162float(hi));
    size_t base = (size_t)o * 768;
    B2[base + d]       = hi;
    B2[base + 256 + d] = lo;
    B2[base + 512 + d] = hi;
}

// ============================================================================
// bf16 mma.sync GEMM, 3-stage cp.async pipeline (BM=128, BN=128, BK=64)
// R10-proven mainloop: issue stage it+2, wait, sync, compute, sync.
// ============================================================================
static constexpr int STAGES      = 3;
static constexpr int STAGE_BYTES = 32768;
static constexpr int SMEM_GEMM   = STAGES * STAGE_BYTES;  // 96KB

__global__ void __launch_bounds__(256, 2)
gemm_bf16_mma(const __nv_bfloat16* __restrict__ A, int lda,
              const __nv_bfloat16* __restrict__ B, int ldb,
              float* __restrict__ C, int ldc, int Ktot) {
    extern __shared__ char smem[];
    const uint32_t sb = smem_u32(smem);
    const int tid  = threadIdx.x;
    const int wid  = tid >> 5, lane = tid & 31;
    const int wm   = wid >> 2, wn = wid & 3;
    const int m0   = blockIdx.y * 128;
    const int n0   = blockIdx.x * 128;

    float acc[4][4][4];
    #pragma unroll
    for (int i = 0; i < 4; i++)
        #pragma unroll
        for (int j = 0; j < 4; j++)
            #pragma unroll
            for (int q = 0; q < 4; q++) acc[i][j][q] = 0.f;

    const int r  = tid >> 3;
    const int cc = tid & 7;
    const int niter = Ktot / 64;

    auto load_stage = [&](int it) {
        const int k0 = it * 64;
        const uint32_t sA = sb + (it % STAGES) * STAGE_BYTES;
        const uint32_t sB = sA + 16384;
        #pragma unroll
        for (int rep = 0; rep < 4; rep++) {
            uint32_t off = SWZ128((uint32_t)((r + rep * 32) * 128 + cc * 16));
            cp_async16(sA + off, A + (size_t)(m0 + r + rep * 32) * lda + k0 + cc * 8);
            cp_async16(sB + off, B + (size_t)(n0 + r + rep * 32) * ldb + k0 + cc * 8);
        }
        cp_commit();
    };

    load_stage(0);
    if (niter > 1) load_stage(1);

    const int arow = wm * 64 + (lane & 15);
    const int acol = ((lane >> 4) & 1) * 16;
    const int brow = wn * 32 + ((lane >> 4) & 1) * 8 + (lane & 7);
    const int bcol = ((lane >> 3) & 1) * 16;

    for (int it = 0; it < niter; ++it) {
        if (it + 2 < niter) { load_stage(it + 2); cp_wait<2>(); }
        else if (it + 1 < niter) cp_wait<1>();
        else cp_wait<0>();
        __syncthreads();

        const uint32_t sA = sb + (it % STAGES) * STAGE_BYTES;
        const uint32_t sB = sA + 16384;

        #pragma unroll
        for (int kk = 0; kk < 4; kk++) {
            uint32_t a[4][4], b[2][4];
            #pragma unroll
            for (int mi = 0; mi < 4; mi++) {
                uint32_t off = SWZ128((uint32_t)((arow + mi * 16) * 128 + kk * 32 + acol));
                ldsm_x4(a[mi], sA + off);
            }
            #pragma unroll
            for (int nt = 0; nt < 2; nt++) {
                uint32_t off = SWZ128((uint32_t)((brow + nt * 16) * 128 + kk * 32 + bcol));
                ldsm_x4(b[nt], sB + off);
            }
            #pragma unroll
            for (int mi = 0; mi < 4; mi++)
                #pragma unroll
                for (int ni = 0; ni < 4; ni++)
                    mma16816(acc[mi][ni], a[mi],
                             b[ni >> 1][(ni & 1) * 2], b[ni >> 1][(ni & 1) * 2 + 1]);
        }
        __syncthreads();
    }

    const int g = lane >> 2, t = lane & 3;
    #pragma unroll
    for (int mi = 0; mi < 4; mi++) {
        #pragma unroll
        for (int ni = 0; ni < 4; ni++) {
            int row = m0 + wm * 64 + mi * 16 + g;
            int col = n0 + wn * 32 + ni * 8 + t * 2;
            float2* p0 = reinterpret_cast<float2*>(C + (size_t)row * ldc + col);
            float2* p1 = reinterpret_cast<float2*>(C + (size_t)(row + 8) * ldc + col);
            *p0 = make_float2(acc[mi][ni][0], acc[mi][ni][1]);
            *p1 = make_float2(acc[mi][ni][2], acc[mi][ni][3]);
        }
    }
}

// ============================================================================
// Big GEMM with FUSED final epilogue (R10 mainloop).
//   A = adj bf16 [NN x 4096]; B = interleaved Ct [512 x 4096].
//   acc column pairs = (U'_c, V'_c), c = col>>1.
//   out[i,c] = relu( HW[i,c] + (SW[c] + a_i*U' - V') / Z_i + bt[c] )
// ============================================================================
__global__ void __launch_bounds__(256, 2)
gemm_big_fused(const __nv_bfloat16* __restrict__ A,
               const __nv_bfloat16* __restrict__ B,
               const float* __restrict__ HW,
               const float* __restrict__ av, const float* __restrict__ uv,
               const float* __restrict__ vv, const float* __restrict__ SW,
               const float* __restrict__ bt, float* __restrict__ out) {
    extern __shared__ char smem[];
    const uint32_t sb = smem_u32(smem);
    const int tid  = threadIdx.x;
    const int wid  = tid >> 5, lane = tid & 31;
    const int wm   = wid >> 2, wn = wid & 3;
    const int m0   = blockIdx.y * 128;
    const int n0   = blockIdx.x * 128;

    float acc[4][4][4];
    #pragma unroll
    for (int i = 0; i < 4; i++)
        #pragma unroll
        for (int j = 0; j < 4; j++)
            #pragma unroll
            for (int q = 0; q < 4; q++) acc[i][j][q] = 0.f;

    const int r  = tid >> 3;
    const int cc = tid & 7;
    const int niter = MM / 64;

    auto load_stage = [&](int it) {
        const int k0 = it * 64;
        const uint32_t sA = sb + (it % STAGES) * STAGE_BYTES;
        const uint32_t sB = sA + 16384;
        #pragma unroll
        for (int rep = 0; rep < 4; rep++) {
            uint32_t off = SWZ128((uint32_t)((r + rep * 32) * 128 + cc * 16));
            cp_async16(sA + off, A + (size_t)(m0 + r + rep * 32) * MM + k0 + cc * 8);
            cp_async16(sB + off, B + (size_t)(n0 + r + rep * 32) * MM + k0 + cc * 8);
        }
        cp_commit();
    };

    load_stage(0);
    load_stage(1);

    const int arow = wm * 64 + (lane & 15);
    const int acol = ((lane >> 4) & 1) * 16;
    const int brow = wn * 32 + ((lane >> 4) & 1) * 8 + (lane & 7);
    const int bcol = ((lane >> 3) & 1) * 16;

    for (int it = 0; it < niter; ++it) {
        if (it + 2 < niter) { load_stage(it + 2); cp_wait<2>(); }
        else if (it + 1 < niter) cp_wait<1>();
        else cp_wait<0>();
        __syncthreads();

        const uint32_t sA = sb + (it % STAGES) * STAGE_BYTES;
        const uint32_t sB = sA + 16384;

        #pragma unroll
        for (int kk = 0; kk < 4; kk++) {
            uint32_t a[4][4], b[2][4];
            #pragma unroll
            for (int mi = 0; mi < 4; mi++) {
                uint32_t off = SWZ128((uint32_t)((arow + mi * 16) * 128 + kk * 32 + acol));
                ldsm_x4(a[mi], sA + off);
            }
            #pragma unroll
            for (int nt = 0; nt < 2; nt++) {
                uint32_t off = SWZ128((uint32_t)((brow + nt * 16) * 128 + kk * 32 + bcol));
                ldsm_x4(b[nt], sB + off);
            }
            #pragma unroll
            for (int mi = 0; mi < 4; mi++)
                #pragma unroll
                for (int ni = 0; ni < 4; ni++)
                    mma16816(acc[mi][ni], a[mi],
                             b[ni >> 1][(ni & 1) * 2], b[ni >> 1][(ni & 1) * 2 + 1]);
        }
        __syncthreads();
    }

    // ---- fused final epilogue ----
    const int g = lane >> 2, t = lane & 3;
    #pragma unroll
    for (int mi = 0; mi < 4; mi++) {
        int row0 = m0 + wm * 64 + mi * 16 + g;
        int row1 = row0 + 8;
        float a0 = av[row0], a1 = av[row1];
        float iz0 = __fdividef(1.f, ((float)MM - vv[row0]) + a0 * uv[row0]);
        float iz1 = __fdividef(1.f, ((float)MM - vv[row1]) + a1 * uv[row1]);
        #pragma unroll
        for (int ni = 0; ni < 4; ni++) {
            int col = n0 + wn * 32 + ni * 8 + t * 2;   // even interleaved col
            int c   = col >> 1;                        // output column
            float sw = SW[c], btc = bt[c];
            float o0 = HW[(size_t)row0 * OO + c]
                     + (sw + a0 * acc[mi][ni][0] - acc[mi][ni][1]) * iz0 + btc;
            float o1 = HW[(size_t)row1 * OO + c]
                     + (sw + a1 * acc[mi][ni][2] - acc[mi][ni][3]) * iz1 + btc;
            out[(size_t)row0 * OO + c] = fmaxf(o0, 0.f);
            out[(size_t)row1 * OO + c] = fmaxf(o1, 0.f);
        }
    }
}

// ============================================================================
// Host launcher — conv_adj (DRAM) overlapped with HW GEMM (tensor) + preps
// ============================================================================
extern "C" void kernel_launch(void* const* d_in, const int* in_sizes, int n_in,
                              void* d_out, int out_size) {
    const float* Hf  = (const float*)d_in[0];
    const float* Hc  = (const float*)d_in[1];
    const float* adj = (const float*)d_in[2];
    const float* wa  = (const float*)d_in[3];
    const float* ba  = (const float*)d_in[4];
    const float* Wt  = (const float*)d_in[5];
    const float* bt  = (const float*)d_in[6];
    float* out = (float*)d_out;

    (void)in_sizes; (void)n_in; (void)out_size;

    __nv_bfloat16 *adjbf, *Ct, *A2, *B2;
    float *G, *HW, *a, *b, *u, *v, *SW;
    cudaGetSymbolAddress((void**)&adjbf, g_adjbf);
    cudaGetSymbolAddress((void**)&Ct,  g_Ct);
    cudaGetSymbolAddress((void**)&A2,  g_A2);
    cudaGetSymbolAddress((void**)&B2,  g_B2);
    cudaGetSymbolAddress((void**)&G,   g_G);
    cudaGetSymbolAddress((void**)&HW,  g_HW);
    cudaGetSymbolAddress((void**)&a,   g_a);
    cudaGetSymbolAddress((void**)&b,   g_b);
    cudaGetSymbolAddress((void**)&u,   g_u);
    cudaGetSymbolAddress((void**)&v,   g_v);
    cudaGetSymbolAddress((void**)&SW,  g_SW);

    cudaFuncSetAttribute(gemm_bf16_mma,
                         cudaFuncAttributeMaxDynamicSharedMemorySize, SMEM_GEMM);
    cudaFuncSetAttribute(gemm_big_fused,
                         cudaFuncAttributeMaxDynamicSharedMemorySize, SMEM_GEMM);

    cudaStream_t s2;
    cudaStreamCreateWithFlags(&s2, cudaStreamNonBlocking);
    cudaEvent_t ev0, ev1;
    cudaEventCreateWithFlags(&ev0, cudaEventDisableTiming);
    cudaEventCreateWithFlags(&ev1, cudaEventDisableTiming);

    // [main] b_j = exp(Hc[j].wa[256:])  (+ SW zero)
    prep_b<<<(MM * 32 + 255) / 256, 256>>>(Hc, wa + DD, b, SW);

    // fork s2 (needs b): adj -> bf16, u = adj@b, v = adj@1  (DRAM-bound)
    cudaEventRecord(ev0, 0);
    cudaStreamWaitEvent(s2, ev0, 0);
    conv_adj<<<NN, 256, 0, s2>>>(adj, b, adjbf, u, v);
    cudaEventRecord(ev1, s2);

    // [main] tensor-bound + small DRAM work, concurrent with conv_adj:
    build_A2_a<<<NN, 256>>>(Hf, wa, ba, A2, a);
    build_B2<<<OO, 256>>>(Wt, B2);
    gemm_bf16_mma<<<dim3(2, NN / 128), 256, SMEM_GEMM>>>(
        A2, 768, B2, 768, HW, 256, 768);            // HW = Hf @ Wt^T
    gemm_G<<<MM / 8, 256>>>(Hc, Wt, G);             // G = Hc @ Wt^T
    build_Ct<<<dim3(16, 512), 256>>>(b, G, Ct, SW); // interleaved Ct + SW

    // join conv_adj, then the big fused GEMM
    cudaStreamWaitEvent(0, ev1, 0);
    gemm_big_fused<<<dim3(4, NN / 128), 256, SMEM_GEMM>>>(
        adjbf, Ct, HW, a, u, v, SW, bt, out);
}